// round 2
// baseline (speedup 1.0000x reference)
#include <cuda_runtime.h>
#include <math.h>

#define NN 100000
#define EE 1200000
#define CC 64
#define HH 64
#define OUTC 10
#define GG 128
#define LL 3
#define EPSBN 1e-5f

// ---------------- scratch (device globals) ----------------
__device__ float g_h [NN * HH];   // node features (post-ReLU)
__device__ float g_hw[NN * HH];   // aggregated A (pre-GEMM)
__device__ int   g_outdeg[NN];
__device__ int   g_indeg [NN];
__device__ int   g_rowptr[NN + 1];
__device__ int   g_cur   [NN];
__device__ int   g_col   [EE];
__device__ float g_dis   [NN];
__device__ int   g_bsum  [128];
__device__ int   g_boff  [128];
__device__ float g_ssum  [HH];
__device__ float g_ssq   [HH];
__device__ float g_Wp    [HH * HH]; // feat layer: diag(s)*W folded
__device__ float g_bias  [HH];      // feat layer: t@W + b_feat
__device__ float g_sc    [HH];      // conv layers: BN scale
__device__ float g_sh    [HH];      // conv layers: BN shift
__device__ float g_hg    [GG * HH];

// packed dual-FMA (sm_100+): d += a * b elementwise on float2
__device__ __forceinline__ void fma2(float2& d, float2 a, float2 b) {
    unsigned long long& dd = reinterpret_cast<unsigned long long&>(d);
    asm("fma.rn.f32x2 %0, %1, %2, %0;"
        : "+l"(dd)
        : "l"(reinterpret_cast<const unsigned long long&>(a)),
          "l"(reinterpret_cast<const unsigned long long&>(b)));
}

// ---------------- setup: degrees, dis, CSR ----------------
__global__ void k_zero_deg() {
    int i = blockIdx.x * blockDim.x + threadIdx.x;
    if (i < NN) { g_outdeg[i] = 0; g_indeg[i] = 0; }
    if (i < 64) { g_ssum[i] = 0.f; g_ssq[i] = 0.f; }
}

__global__ void k_hist(const int* __restrict__ src, const int* __restrict__ dst) {
    int e = blockIdx.x * blockDim.x + threadIdx.x;
    if (e < EE) {
        atomicAdd(&g_indeg[dst[e]], 1);
        atomicAdd(&g_outdeg[src[e]], 1);
    }
}

__global__ void k_dis() {
    int i = blockIdx.x * blockDim.x + threadIdx.x;
    if (i < NN) g_dis[i] = rsqrtf((float)g_outdeg[i] + 1.0f);
}

__global__ void k_scan1() {
    __shared__ int sb[1024];
    int t = threadIdx.x;
    int i = blockIdx.x * 1024 + t;
    int v = (i < NN) ? g_indeg[i] : 0;
    sb[t] = v;
    __syncthreads();
    for (int off = 1; off < 1024; off <<= 1) {
        int x = (t >= off) ? sb[t - off] : 0;
        __syncthreads();
        sb[t] += x;
        __syncthreads();
    }
    if (i < NN) g_rowptr[i] = sb[t] - v;
    if (t == 1023) g_bsum[blockIdx.x] = sb[1023];
}

__global__ void k_scan2(int nb) {
    int run = 0;
    for (int b = 0; b < nb; b++) { g_boff[b] = run; run += g_bsum[b]; }
    g_rowptr[NN] = run;
}

__global__ void k_scan3() {
    int i = blockIdx.x * 1024 + threadIdx.x;
    if (i < NN) {
        int v = g_rowptr[i] + g_boff[blockIdx.x];
        g_rowptr[i] = v;
        g_cur[i] = v;
    }
}

__global__ void k_fill(const int* __restrict__ src, const int* __restrict__ dst) {
    int e = blockIdx.x * blockDim.x + threadIdx.x;
    if (e < EE) {
        int d = dst[e];
        int p = atomicAdd(&g_cur[d], 1);
        g_col[p] = src[e];
    }
}

// ---------------- colstats for x only ----------------
__global__ void k_colstats(const float* __restrict__ A, int n) {
    __shared__ float rs[256], rq[256];
    int c  = threadIdx.x & 63;
    int rr = threadIdx.x >> 6;
    int rbeg = blockIdx.x * 512;
    int rend = rbeg + 512; if (rend > n) rend = n;
    float s = 0.f, q = 0.f;
    for (int r = rbeg + rr; r < rend; r += 4) {
        float v = A[(size_t)r * 64 + c];
        s += v; q += v * v;
    }
    rs[threadIdx.x] = s; rq[threadIdx.x] = q;
    __syncthreads();
    if (threadIdx.x < 64) {
        float S = rs[threadIdx.x] + rs[threadIdx.x + 64] + rs[threadIdx.x + 128] + rs[threadIdx.x + 192];
        float Q = rq[threadIdx.x] + rq[threadIdx.x + 64] + rq[threadIdx.x + 128] + rq[threadIdx.x + 192];
        atomicAdd(&g_ssum[threadIdx.x], S);
        atomicAdd(&g_ssq [threadIdx.x], Q);
    }
}

// feat layer: fold BN(x) into W (Wp=diag(s)W, g_bias=t@W+b_feat); zero stats
__global__ void k_fold_feat(const float* __restrict__ gam, const float* __restrict__ bet,
                            const float* __restrict__ W, const float* __restrict__ b2) {
    __shared__ float s_s[64], s_t[64];
    int c = threadIdx.x;
    float invn = 1.0f / (float)NN;
    float mu  = g_ssum[c] * invn;
    float var = fmaxf(g_ssq[c] * invn - mu * mu, 0.f);
    float inv = rsqrtf(var + EPSBN);
    float sc = inv * gam[c];
    s_s[c] = sc;
    s_t[c] = bet[c] - mu * sc;
    __syncthreads();
    float bv = 0.f;
    #pragma unroll 8
    for (int k = 0; k < 64; k++) {
        float w = W[k * 64 + c];
        g_Wp[k * 64 + c] = s_s[k] * w;
        bv += s_t[k] * w;
    }
    g_bias[c] = bv + b2[c];
    g_ssum[c] = 0.f; g_ssq[c] = 0.f;
}

// conv layers: stats -> per-column scale/shift; zero stats
__global__ void k_scale(const float* __restrict__ gam, const float* __restrict__ bet) {
    int c = threadIdx.x;
    float invn = 1.0f / (float)NN;
    float mu  = g_ssum[c] * invn;
    float var = fmaxf(g_ssq[c] * invn - mu * mu, 0.f);
    float inv = rsqrtf(var + EPSBN);
    float sc = inv * gam[c];
    g_sc[c] = sc;
    g_sh[c] = bet[c] - mu * sc;
    g_ssum[c] = 0.f; g_ssq[c] = 0.f;
}

// ---------------- GEMM: out = relu(A @ W + bias), fused next-layer col stats ----------------
// dyn smem: sA[8192] | sW2[8192] | sredS[512] | sredQ[512]
__global__ __launch_bounds__(256)
void k_gemm(const float* __restrict__ A, const float* __restrict__ W,
            const float* __restrict__ bias, float* __restrict__ out,
            int n, int doStats) {
    extern __shared__ float sm[];
    float* sA    = sm;
    float* sW2   = sm + 8192;
    float* sredS = sm + 16384;
    float* sredQ = sm + 16896;
    int tid = threadIdx.x;
    int rowBase = blockIdx.x * 128;

    // W duplicated: sW2[k*128 + 2j] = sW2[k*128 + 2j+1] = W[k][j]
    for (int i = tid; i < 4096; i += 256) {
        float w = W[i];
        int k = i >> 6, j = i & 63;
        sW2[k * 128 + 2 * j]     = w;
        sW2[k * 128 + 2 * j + 1] = w;
    }

    int lane = tid & 31, wid = tid >> 5;
    int k0 = wid * 8;
    #pragma unroll
    for (int rp = 0; rp < 4; rp++) {
        int r = rp * 32 + lane;
        int grow = rowBase + r;
        float4 v0 = make_float4(0.f, 0.f, 0.f, 0.f), v1 = v0;
        if (grow < n) {
            const float4* p = (const float4*)(A + (size_t)grow * 64 + k0);
            v0 = p[0]; v1 = p[1];
        }
        sA[(k0 + 0) * 128 + r] = v0.x;
        sA[(k0 + 1) * 128 + r] = v0.y;
        sA[(k0 + 2) * 128 + r] = v0.z;
        sA[(k0 + 3) * 128 + r] = v0.w;
        sA[(k0 + 4) * 128 + r] = v1.x;
        sA[(k0 + 5) * 128 + r] = v1.y;
        sA[(k0 + 6) * 128 + r] = v1.z;
        sA[(k0 + 7) * 128 + r] = v1.w;
    }
    __syncthreads();

    int cx = (tid & 15) * 4;   // 4 output cols
    int ry = (tid >> 4) * 8;   // 8 output rows (4 packed pairs)
    float2 acc[4][4];
    #pragma unroll
    for (int i = 0; i < 4; i++)
        #pragma unroll
        for (int j = 0; j < 4; j++) acc[i][j] = make_float2(0.f, 0.f);

    #pragma unroll
    for (int k = 0; k < 64; k++) {
        float4 a03 = *(const float4*)(sA + k * 128 + ry);
        float4 a47 = *(const float4*)(sA + k * 128 + ry + 4);
        float4 wA  = *(const float4*)(sW2 + k * 128 + cx * 2);
        float4 wB  = *(const float4*)(sW2 + k * 128 + cx * 2 + 4);
        float2 ap[4] = { make_float2(a03.x, a03.y), make_float2(a03.z, a03.w),
                         make_float2(a47.x, a47.y), make_float2(a47.z, a47.w) };
        float2 wp[4] = { make_float2(wA.x, wA.y), make_float2(wA.z, wA.w),
                         make_float2(wB.x, wB.y), make_float2(wB.z, wB.w) };
        #pragma unroll
        for (int i = 0; i < 4; i++) {
            fma2(acc[i][0], ap[i], wp[0]);
            fma2(acc[i][1], ap[i], wp[1]);
            fma2(acc[i][2], ap[i], wp[2]);
            fma2(acc[i][3], ap[i], wp[3]);
        }
    }

    float b0 = bias[cx], b1 = bias[cx + 1], b2 = bias[cx + 2], b3 = bias[cx + 3];
    float cs[4] = {0.f, 0.f, 0.f, 0.f}, cq[4] = {0.f, 0.f, 0.f, 0.f};
    #pragma unroll
    for (int i = 0; i < 4; i++) {
        int r0 = rowBase + ry + 2 * i;
        float4 oA, oB;
        oA.x = fmaxf(acc[i][0].x + b0, 0.f);
        oA.y = fmaxf(acc[i][1].x + b1, 0.f);
        oA.z = fmaxf(acc[i][2].x + b2, 0.f);
        oA.w = fmaxf(acc[i][3].x + b3, 0.f);
        oB.x = fmaxf(acc[i][0].y + b0, 0.f);
        oB.y = fmaxf(acc[i][1].y + b1, 0.f);
        oB.z = fmaxf(acc[i][2].y + b2, 0.f);
        oB.w = fmaxf(acc[i][3].y + b3, 0.f);
        if (r0 < n) {
            *(float4*)(out + (size_t)r0 * 64 + cx) = oA;
            cs[0] += oA.x; cq[0] += oA.x * oA.x;
            cs[1] += oA.y; cq[1] += oA.y * oA.y;
            cs[2] += oA.z; cq[2] += oA.z * oA.z;
            cs[3] += oA.w; cq[3] += oA.w * oA.w;
        }
        if (r0 + 1 < n) {
            *(float4*)(out + (size_t)(r0 + 1) * 64 + cx) = oB;
            cs[0] += oB.x; cq[0] += oB.x * oB.x;
            cs[1] += oB.y; cq[1] += oB.y * oB.y;
            cs[2] += oB.z; cq[2] += oB.z * oB.z;
            cs[3] += oB.w; cq[3] += oB.w * oB.w;
        }
    }

    if (doStats) {
        #pragma unroll
        for (int j = 0; j < 4; j++) {
            cs[j] += __shfl_xor_sync(0xFFFFFFFFu, cs[j], 16);
            cq[j] += __shfl_xor_sync(0xFFFFFFFFu, cq[j], 16);
        }
        if (lane < 16) {
            #pragma unroll
            for (int j = 0; j < 4; j++) {
                sredS[wid * 64 + cx + j] = cs[j];
                sredQ[wid * 64 + cx + j] = cq[j];
            }
        }
        __syncthreads();
        if (tid < 64) {
            float S = 0.f, Q = 0.f;
            #pragma unroll
            for (int w = 0; w < 8; w++) { S += sredS[w * 64 + tid]; Q += sredQ[w * 64 + tid]; }
            atomicAdd(&g_ssum[tid], S);
            atomicAdd(&g_ssq [tid], Q);
        }
    }
}

// ---------------- aggregation: A = sc ∘ (Σ_e w·h[src] + di²·h[i]) + ws·sh ----------------
__global__ __launch_bounds__(256)
void k_agg() {
    int gtid = blockIdx.x * 256 + threadIdx.x;
    int i = gtid >> 5;
    int lane = gtid & 31;
    if (i >= NN) return;
    int c0 = lane * 2;
    float di = g_dis[i];
    int e = g_rowptr[i], end = g_rowptr[i + 1];
    float a0 = 0.f, a1 = 0.f, ws = 0.f;
    const float* __restrict__ in = g_h;

    for (; e + 4 <= end; e += 4) {
        int s0 = g_col[e], s1 = g_col[e + 1], s2 = g_col[e + 2], s3 = g_col[e + 3];
        float w0 = g_dis[s0], w1 = g_dis[s1], w2 = g_dis[s2], w3 = g_dis[s3];
        float2 v0 = *(const float2*)&in[(size_t)s0 * 64 + c0];
        float2 v1 = *(const float2*)&in[(size_t)s1 * 64 + c0];
        float2 v2 = *(const float2*)&in[(size_t)s2 * 64 + c0];
        float2 v3 = *(const float2*)&in[(size_t)s3 * 64 + c0];
        w0 *= di; w1 *= di; w2 *= di; w3 *= di;
        a0 = fmaf(w0, v0.x, a0); a1 = fmaf(w0, v0.y, a1);
        a0 = fmaf(w1, v1.x, a0); a1 = fmaf(w1, v1.y, a1);
        a0 = fmaf(w2, v2.x, a0); a1 = fmaf(w2, v2.y, a1);
        a0 = fmaf(w3, v3.x, a0); a1 = fmaf(w3, v3.y, a1);
        ws += w0 + w1 + w2 + w3;
    }
    for (; e < end; e++) {
        int s = g_col[e];
        float w = di * g_dis[s];
        float2 v = *(const float2*)&in[(size_t)s * 64 + c0];
        a0 = fmaf(w, v.x, a0);
        a1 = fmaf(w, v.y, a1);
        ws += w;
    }
    {   // self loop
        float w = di * di;
        float2 v = *(const float2*)&in[(size_t)i * 64 + c0];
        a0 = fmaf(w, v.x, a0);
        a1 = fmaf(w, v.y, a1);
        ws += w;
    }
    float o0 = g_sc[c0]     * a0 + ws * g_sh[c0];
    float o1 = g_sc[c0 + 1] * a1 + ws * g_sh[c0 + 1];
    *(float2*)&g_hw[(size_t)i * 64 + c0] = make_float2(o0, o1);
}

// ---------------- pooling ----------------
__global__ void k_zerohg() {
    int i = blockIdx.x * blockDim.x + threadIdx.x;
    if (i < GG * HH) g_hg[i] = 0.f;
}

__global__ void k_pool(const int* __restrict__ batch) {
    int gtid = blockIdx.x * 256 + threadIdx.x;
    int warp = gtid >> 5;
    int lane = gtid & 31;
    int n0 = warp * 16;
    if (n0 >= NN) return;
    int nend = n0 + 16; if (nend > NN) nend = NN;
    int c0 = lane * 2;
    float a0 = 0.f, a1 = 0.f;
    int curg = batch[n0];
    for (int nd = n0; nd < nend; nd++) {
        int g = batch[nd];
        if (g != curg) {
            atomicAdd(&g_hg[curg * 64 + c0],     a0);
            atomicAdd(&g_hg[curg * 64 + c0 + 1], a1);
            a0 = 0.f; a1 = 0.f; curg = g;
        }
        float2 v = *(const float2*)&g_h[(size_t)nd * 64 + c0];
        a0 += v.x; a1 += v.y;
    }
    atomicAdd(&g_hg[curg * 64 + c0],     a0);
    atomicAdd(&g_hg[curg * 64 + c0 + 1], a1);
}

// ---------------- final head ----------------
__global__ __launch_bounds__(256, 1)
void k_final(const float* __restrict__ bn1g, const float* __restrict__ bn1b,
             const float* __restrict__ Wfc,  const float* __restrict__ bfc,
             const float* __restrict__ bn2g, const float* __restrict__ bn2b,
             const float* __restrict__ Wcls, const float* __restrict__ bcls,
             float* __restrict__ out) {
    __shared__ float sA[128 * 65];
    __shared__ float red[256], red2[256];
    __shared__ float s_s[64], s_t[64];
    int tid = threadIdx.x;
    int c = tid & 63, rr = tid >> 6;

    for (int i = tid; i < 128 * 64; i += 256)
        sA[(i >> 6) * 65 + (i & 63)] = g_hg[i];
    __syncthreads();

    float s = 0.f, q = 0.f;
    for (int r = rr; r < 128; r += 4) {
        float v = sA[r * 65 + c];
        s += v; q += v * v;
    }
    red[tid] = s; red2[tid] = q;
    __syncthreads();
    if (tid < 64) {
        float S = red [tid] + red [tid + 64] + red [tid + 128] + red [tid + 192];
        float Q = red2[tid] + red2[tid + 64] + red2[tid + 128] + red2[tid + 192];
        float mu = S * (1.f / 128.f);
        float var = fmaxf(Q * (1.f / 128.f) - mu * mu, 0.f);
        float inv = rsqrtf(var + EPSBN);
        float sc = inv * bn1g[tid];
        s_s[tid] = sc;
        s_t[tid] = bn1b[tid] - mu * sc;
    }
    __syncthreads();
    for (int r = rr; r < 128; r += 4)
        sA[r * 65 + c] = sA[r * 65 + c] * s_s[c] + s_t[c];
    __syncthreads();

    float wreg[64];
    #pragma unroll
    for (int k = 0; k < 64; k++) wreg[k] = Wfc[k * 64 + c];
    float acc[32];
    for (int ri = 0; ri < 32; ri++) {
        int r = rr + ri * 4;
        float a = bfc[c];
        #pragma unroll
        for (int k = 0; k < 64; k++) a = fmaf(sA[r * 65 + k], wreg[k], a);
        acc[ri] = fmaxf(a, 0.f);
    }
    __syncthreads();
    for (int ri = 0; ri < 32; ri++) sA[(rr + ri * 4) * 65 + c] = acc[ri];
    __syncthreads();

    s = 0.f; q = 0.f;
    for (int r = rr; r < 128; r += 4) {
        float v = sA[r * 65 + c];
        s += v; q += v * v;
    }
    red[tid] = s; red2[tid] = q;
    __syncthreads();
    if (tid < 64) {
        float S = red [tid] + red [tid + 64] + red [tid + 128] + red [tid + 192];
        float Q = red2[tid] + red2[tid + 64] + red2[tid + 128] + red2[tid + 192];
        float mu = S * (1.f / 128.f);
        float var = fmaxf(Q * (1.f / 128.f) - mu * mu, 0.f);
        float inv = rsqrtf(var + EPSBN);
        float sc = inv * bn2g[tid];
        s_s[tid] = sc;
        s_t[tid] = bn2b[tid] - mu * sc;
    }
    __syncthreads();

    if (tid < 128) {
        int r = tid;
        float logits[10];
        #pragma unroll
        for (int j = 0; j < 10; j++) logits[j] = bcls[j];
        for (int k = 0; k < 64; k++) {
            float v = sA[r * 65 + k] * s_s[k] + s_t[k];
            #pragma unroll
            for (int j = 0; j < 10; j++)
                logits[j] = fmaf(v, Wcls[k * 10 + j], logits[j]);
        }
        float m = logits[0];
        #pragma unroll
        for (int j = 1; j < 10; j++) m = fmaxf(m, logits[j]);
        float se = 0.f;
        #pragma unroll
        for (int j = 0; j < 10; j++) se += expf(logits[j] - m);
        float lse = logf(se) + m;
        #pragma unroll
        for (int j = 0; j < 10; j++) out[r * 10 + j] = logits[j] - lse;
    }
}

// ---------------- host launch ----------------
extern "C" void kernel_launch(void* const* d_in, const int* in_sizes, int n_in,
                              void* d_out, int out_size) {
    const float* x         = (const float*)d_in[0];
    const int*   ei        = (const int*)  d_in[1];
    const int*   batch     = (const int*)  d_in[2];
    const float* bn_feat_g = (const float*)d_in[3];
    const float* bn_feat_b = (const float*)d_in[4];
    const float* W_feat    = (const float*)d_in[5];
    const float* b_feat    = (const float*)d_in[6];
    const float* conv_bn_g = (const float*)d_in[7];
    const float* conv_bn_b = (const float*)d_in[8];
    const float* conv_W    = (const float*)d_in[9];
    const float* conv_b    = (const float*)d_in[10];
    const float* bn_fc_g   = (const float*)d_in[11];
    const float* bn_fc_b   = (const float*)d_in[12];
    const float* W_fc      = (const float*)d_in[13];
    const float* b_fc      = (const float*)d_in[14];
    const float* bn_hid_g  = (const float*)d_in[15];
    const float* bn_hid_b  = (const float*)d_in[16];
    const float* W_cls     = (const float*)d_in[17];
    const float* b_cls     = (const float*)d_in[18];
    float* out = (float*)d_out;

    void *ph_v, *phw_v, *pWp_v, *pbias_v;
    cudaGetSymbolAddress(&ph_v,   g_h);
    cudaGetSymbolAddress(&phw_v,  g_hw);
    cudaGetSymbolAddress(&pWp_v,  g_Wp);
    cudaGetSymbolAddress(&pbias_v, g_bias);
    float* ph    = (float*)ph_v;
    float* phw   = (float*)phw_v;
    float* pWp   = (float*)pWp_v;
    float* pbias = (float*)pbias_v;

    const int* src = ei;
    const int* dst = ei + EE;

    const int nbScan = (NN + 1023) / 1024;
    const int nbNode = (NN + 255) / 256;
    const int nbEdge = (EE + 255) / 256;
    const int nbStat = (NN + 511) / 512;
    const int nbGemm = (NN + 127) / 128;
    const int nbAgg  = (NN * 32 + 255) / 256;
    const int nbPool = (((NN + 15) / 16) * 32 + 255) / 256;
    const int GEMM_SMEM = (8192 + 8192 + 512 + 512) * 4;  // 69632 B

    cudaFuncSetAttribute(k_gemm, cudaFuncAttributeMaxDynamicSharedMemorySize, GEMM_SMEM);

    // ---- CSR build ----
    k_zero_deg<<<nbNode, 256>>>();
    k_hist<<<nbEdge, 256>>>(src, dst);
    k_dis<<<nbNode, 256>>>();
    k_scan1<<<nbScan, 1024>>>();
    k_scan2<<<1, 1>>>(nbScan);
    k_scan3<<<nbScan, 1024>>>();
    k_fill<<<nbEdge, 256>>>(src, dst);

    // ---- feat layer: h = relu(BN(x) @ W_feat + b_feat), stats fused ----
    k_colstats<<<nbStat, 256>>>(x, NN);
    k_fold_feat<<<1, 64>>>(bn_feat_g, bn_feat_b, W_feat, b_feat);
    k_gemm<<<nbGemm, 256, GEMM_SMEM>>>(x, pWp, pbias, ph, NN, 1);

    // ---- conv layers: agg(BN folded) -> GEMM(+bias, relu, stats) ----
    for (int l = 0; l < LL; l++) {
        k_scale<<<1, 64>>>(conv_bn_g + l * HH, conv_bn_b + l * HH);
        k_agg<<<nbAgg, 256>>>();
        k_gemm<<<nbGemm, 256, GEMM_SMEM>>>(phw, conv_W + l * HH * HH,
                                           conv_b + l * HH, ph, NN, (l < LL - 1) ? 1 : 0);
    }

    // ---- pool + head ----
    k_zerohg<<<32, 256>>>();
    k_pool<<<nbPool, 256>>>(batch);
    k_final<<<1, 256>>>(bn_fc_g, bn_fc_b, W_fc, b_fc,
                        bn_hid_g, bn_hid_b, W_cls, b_cls, out);
}

// round 3
// speedup vs baseline: 1.0660x; 1.0660x over previous
#include <cuda_runtime.h>
#include <math.h>

#define NN 100000
#define EE 1200000
#define CC 64
#define HH 64
#define OUTC 10
#define GG 128
#define LL 3
#define EPSBN 1e-5f

// ---------------- scratch (device globals) ----------------
__device__ float g_h [NN * HH];   // buffer 0
__device__ float g_hw[NN * HH];   // buffer 1
__device__ int   g_outdeg[NN];
__device__ int   g_indeg [NN];
__device__ int   g_rowptr[NN + 1];
__device__ int   g_cur   [NN];
__device__ int   g_col   [EE];
__device__ float g_dis   [NN];
__device__ int   g_bsum  [128];
__device__ int   g_boff  [128];
__device__ float g_ssum  [HH];
__device__ float g_ssq   [HH];
__device__ float g_Wp    [HH * HH]; // feat layer: diag(s)*W folded
__device__ float g_bias  [HH];      // feat layer: t@W + b_feat
__device__ float g_sc    [HH];      // conv layers: BN scale
__device__ float g_sh    [HH];      // conv layers: BN shift
__device__ float g_hg    [GG * HH];

// ---------------- setup: degrees, dis, CSR ----------------
__global__ void k_zero_deg() {
    int i = blockIdx.x * blockDim.x + threadIdx.x;
    if (i < NN) { g_outdeg[i] = 0; g_indeg[i] = 0; }
    if (i < 64) { g_ssum[i] = 0.f; g_ssq[i] = 0.f; }
}

__global__ void k_hist(const int* __restrict__ src, const int* __restrict__ dst) {
    int e = blockIdx.x * blockDim.x + threadIdx.x;
    if (e < EE) {
        atomicAdd(&g_indeg[dst[e]], 1);
        atomicAdd(&g_outdeg[src[e]], 1);
    }
}

__global__ void k_dis() {
    int i = blockIdx.x * blockDim.x + threadIdx.x;
    if (i < NN) g_dis[i] = rsqrtf((float)g_outdeg[i] + 1.0f);
}

__global__ void k_scan1() {
    __shared__ int sb[1024];
    int t = threadIdx.x;
    int i = blockIdx.x * 1024 + t;
    int v = (i < NN) ? g_indeg[i] : 0;
    sb[t] = v;
    __syncthreads();
    for (int off = 1; off < 1024; off <<= 1) {
        int x = (t >= off) ? sb[t - off] : 0;
        __syncthreads();
        sb[t] += x;
        __syncthreads();
    }
    if (i < NN) g_rowptr[i] = sb[t] - v;
    if (t == 1023) g_bsum[blockIdx.x] = sb[1023];
}

__global__ void k_scan2(int nb) {
    int run = 0;
    for (int b = 0; b < nb; b++) { g_boff[b] = run; run += g_bsum[b]; }
    g_rowptr[NN] = run;
}

__global__ void k_scan3() {
    int i = blockIdx.x * 1024 + threadIdx.x;
    if (i < NN) {
        int v = g_rowptr[i] + g_boff[blockIdx.x];
        g_rowptr[i] = v;
        g_cur[i] = v;
    }
}

__global__ void k_fill(const int* __restrict__ src, const int* __restrict__ dst) {
    int e = blockIdx.x * blockDim.x + threadIdx.x;
    if (e < EE) {
        int d = dst[e];
        int p = atomicAdd(&g_cur[d], 1);
        g_col[p] = src[e];
    }
}

// ---------------- colstats for x only ----------------
__global__ void k_colstats(const float* __restrict__ A, int n) {
    __shared__ float rs[256], rq[256];
    int c  = threadIdx.x & 63;
    int rr = threadIdx.x >> 6;
    int rbeg = blockIdx.x * 512;
    int rend = rbeg + 512; if (rend > n) rend = n;
    float s = 0.f, q = 0.f;
    for (int r = rbeg + rr; r < rend; r += 4) {
        float v = A[(size_t)r * 64 + c];
        s += v; q += v * v;
    }
    rs[threadIdx.x] = s; rq[threadIdx.x] = q;
    __syncthreads();
    if (threadIdx.x < 64) {
        float S = rs[threadIdx.x] + rs[threadIdx.x + 64] + rs[threadIdx.x + 128] + rs[threadIdx.x + 192];
        float Q = rq[threadIdx.x] + rq[threadIdx.x + 64] + rq[threadIdx.x + 128] + rq[threadIdx.x + 192];
        atomicAdd(&g_ssum[threadIdx.x], S);
        atomicAdd(&g_ssq [threadIdx.x], Q);
    }
}

// feat layer: fold BN(x) into W (Wp=diag(s)W, g_bias=t@W+b_feat); zero stats
__global__ void k_fold_feat(const float* __restrict__ gam, const float* __restrict__ bet,
                            const float* __restrict__ W, const float* __restrict__ b2) {
    __shared__ float s_s[64], s_t[64];
    int c = threadIdx.x;
    float invn = 1.0f / (float)NN;
    float mu  = g_ssum[c] * invn;
    float var = fmaxf(g_ssq[c] * invn - mu * mu, 0.f);
    float inv = rsqrtf(var + EPSBN);
    float sc = inv * gam[c];
    s_s[c] = sc;
    s_t[c] = bet[c] - mu * sc;
    __syncthreads();
    float bv = 0.f;
    #pragma unroll 8
    for (int k = 0; k < 64; k++) {
        float w = W[k * 64 + c];
        g_Wp[k * 64 + c] = s_s[k] * w;
        bv += s_t[k] * w;
    }
    g_bias[c] = bv + b2[c];
    g_ssum[c] = 0.f; g_ssq[c] = 0.f;
}

// conv layers: stats -> per-column scale/shift; zero stats
__global__ void k_scale(const float* __restrict__ gam, const float* __restrict__ bet) {
    int c = threadIdx.x;
    float invn = 1.0f / (float)NN;
    float mu  = g_ssum[c] * invn;
    float var = fmaxf(g_ssq[c] * invn - mu * mu, 0.f);
    float inv = rsqrtf(var + EPSBN);
    float sc = inv * gam[c];
    g_sc[c] = sc;
    g_sh[c] = bet[c] - mu * sc;
    g_ssum[c] = 0.f; g_ssq[c] = 0.f;
}

// ---------------- fused [agg ->] GEMM: out = relu(A @ W + bias), fused col stats ----------------
// mode 0: A-tile loaded from global Ain rows (feat layer)
// mode 1: A-tile produced by GCN aggregation of Ain (gather via CSR), with BN scale/shift folded
__global__ __launch_bounds__(256)
void k_fused(const float* __restrict__ Ain, const float* __restrict__ W,
             const float* __restrict__ bias, float* __restrict__ out,
             int doStats, int mode) {
    __shared__ float sR[128 * 64];   // A-tile, row-major; reused as stats scratch later
    __shared__ float sW[64 * 64];
    int tid = threadIdx.x;
    int rowBase = blockIdx.x * 128;

    for (int i = tid * 4; i < 4096; i += 1024)
        *(float4*)(sW + i) = *(const float4*)(W + i);

    if (mode == 0) {
        // plain copy of 128 rows (zero-pad tail)
        for (int idx = tid; idx < 2048; idx += 256) {
            int r = idx >> 4, q = idx & 15;
            int grow = rowBase + r;
            float4 v = make_float4(0.f, 0.f, 0.f, 0.f);
            if (grow < NN) v = *(const float4*)(Ain + (size_t)grow * 64 + q * 4);
            *(float4*)(sR + r * 64 + q * 4) = v;
        }
    } else {
        // aggregation: warp w handles 16 nodes; lane owns 2 columns
        int w = tid >> 5, lane = tid & 31;
        int c0 = lane * 2;
        float sc0 = g_sc[c0], sc1 = g_sc[c0 + 1];
        float sh0 = g_sh[c0], sh1 = g_sh[c0 + 1];
        for (int t = 0; t < 16; t++) {
            int r = w * 16 + t;
            int i = rowBase + r;
            float o0 = 0.f, o1 = 0.f;
            if (i < NN) {
                float di = g_dis[i];
                int e = g_rowptr[i], end = g_rowptr[i + 1];
                float a0 = 0.f, a1 = 0.f, ws = 0.f;
                for (; e + 4 <= end; e += 4) {
                    int s0 = g_col[e], s1 = g_col[e + 1], s2 = g_col[e + 2], s3 = g_col[e + 3];
                    float w0 = g_dis[s0], w1 = g_dis[s1], w2 = g_dis[s2], w3 = g_dis[s3];
                    float2 v0 = *(const float2*)&Ain[(size_t)s0 * 64 + c0];
                    float2 v1 = *(const float2*)&Ain[(size_t)s1 * 64 + c0];
                    float2 v2 = *(const float2*)&Ain[(size_t)s2 * 64 + c0];
                    float2 v3 = *(const float2*)&Ain[(size_t)s3 * 64 + c0];
                    w0 *= di; w1 *= di; w2 *= di; w3 *= di;
                    a0 = fmaf(w0, v0.x, a0); a1 = fmaf(w0, v0.y, a1);
                    a0 = fmaf(w1, v1.x, a0); a1 = fmaf(w1, v1.y, a1);
                    a0 = fmaf(w2, v2.x, a0); a1 = fmaf(w2, v2.y, a1);
                    a0 = fmaf(w3, v3.x, a0); a1 = fmaf(w3, v3.y, a1);
                    ws += w0 + w1 + w2 + w3;
                }
                for (; e < end; e++) {
                    int s = g_col[e];
                    float wv = di * g_dis[s];
                    float2 v = *(const float2*)&Ain[(size_t)s * 64 + c0];
                    a0 = fmaf(wv, v.x, a0);
                    a1 = fmaf(wv, v.y, a1);
                    ws += wv;
                }
                {   // self loop
                    float wv = di * di;
                    float2 v = *(const float2*)&Ain[(size_t)i * 64 + c0];
                    a0 = fmaf(wv, v.x, a0);
                    a1 = fmaf(wv, v.y, a1);
                    ws += wv;
                }
                o0 = sc0 * a0 + ws * sh0;
                o1 = sc1 * a1 + ws * sh1;
            }
            *(float2*)(sR + r * 64 + c0) = make_float2(o0, o1);
        }
    }
    __syncthreads();

    // ---- GEMM: thread computes rows ry..ry+7 x cols cx..cx+3 ----
    int lane = tid & 31, wid = tid >> 5;
    int cx = (tid & 15) * 4;
    int ry = (tid >> 4) * 8;
    float acc[8][4];
    #pragma unroll
    for (int i = 0; i < 8; i++)
        #pragma unroll
        for (int j = 0; j < 4; j++) acc[i][j] = 0.f;

    #pragma unroll 4
    for (int k = 0; k < 64; k++) {
        float4 w4 = *(const float4*)(sW + k * 64 + cx);
        #pragma unroll
        for (int i = 0; i < 8; i++) {
            float a = sR[(ry + i) * 64 + k];
            acc[i][0] = fmaf(a, w4.x, acc[i][0]);
            acc[i][1] = fmaf(a, w4.y, acc[i][1]);
            acc[i][2] = fmaf(a, w4.z, acc[i][2]);
            acc[i][3] = fmaf(a, w4.w, acc[i][3]);
        }
    }

    float b0 = bias[cx], b1 = bias[cx + 1], b2 = bias[cx + 2], b3 = bias[cx + 3];
    float cs[4] = {0.f, 0.f, 0.f, 0.f}, cq[4] = {0.f, 0.f, 0.f, 0.f};
    #pragma unroll
    for (int i = 0; i < 8; i++) {
        int grow = rowBase + ry + i;
        if (grow < NN) {
            float4 o;
            o.x = fmaxf(acc[i][0] + b0, 0.f);
            o.y = fmaxf(acc[i][1] + b1, 0.f);
            o.z = fmaxf(acc[i][2] + b2, 0.f);
            o.w = fmaxf(acc[i][3] + b3, 0.f);
            *(float4*)(out + (size_t)grow * 64 + cx) = o;
            cs[0] += o.x; cq[0] += o.x * o.x;
            cs[1] += o.y; cq[1] += o.y * o.y;
            cs[2] += o.z; cq[2] += o.z * o.z;
            cs[3] += o.w; cq[3] += o.w * o.w;
        }
    }

    if (doStats) {
        __syncthreads();                 // sR now dead; reuse as scratch
        float* sredS = sR;
        float* sredQ = sR + 512;
        #pragma unroll
        for (int j = 0; j < 4; j++) {
            cs[j] += __shfl_xor_sync(0xFFFFFFFFu, cs[j], 16);
            cq[j] += __shfl_xor_sync(0xFFFFFFFFu, cq[j], 16);
        }
        if (lane < 16) {
            #pragma unroll
            for (int j = 0; j < 4; j++) {
                sredS[wid * 64 + cx + j] = cs[j];
                sredQ[wid * 64 + cx + j] = cq[j];
            }
        }
        __syncthreads();
        if (tid < 64) {
            float S = 0.f, Q = 0.f;
            #pragma unroll
            for (int w = 0; w < 8; w++) { S += sredS[w * 64 + tid]; Q += sredQ[w * 64 + tid]; }
            atomicAdd(&g_ssum[tid], S);
            atomicAdd(&g_ssq [tid], Q);
        }
    }
}

// ---------------- pooling ----------------
__global__ void k_zerohg() {
    int i = blockIdx.x * blockDim.x + threadIdx.x;
    if (i < GG * HH) g_hg[i] = 0.f;
}

__global__ void k_pool(const int* __restrict__ batch, const float* __restrict__ hin) {
    int gtid = blockIdx.x * 256 + threadIdx.x;
    int warp = gtid >> 5;
    int lane = gtid & 31;
    int n0 = warp * 16;
    if (n0 >= NN) return;
    int nend = n0 + 16; if (nend > NN) nend = NN;
    int c0 = lane * 2;
    float a0 = 0.f, a1 = 0.f;
    int curg = batch[n0];
    for (int nd = n0; nd < nend; nd++) {
        int g = batch[nd];
        if (g != curg) {
            atomicAdd(&g_hg[curg * 64 + c0],     a0);
            atomicAdd(&g_hg[curg * 64 + c0 + 1], a1);
            a0 = 0.f; a1 = 0.f; curg = g;
        }
        float2 v = *(const float2*)&hin[(size_t)nd * 64 + c0];
        a0 += v.x; a1 += v.y;
    }
    atomicAdd(&g_hg[curg * 64 + c0],     a0);
    atomicAdd(&g_hg[curg * 64 + c0 + 1], a1);
}

// ---------------- final head ----------------
__global__ __launch_bounds__(256, 1)
void k_final(const float* __restrict__ bn1g, const float* __restrict__ bn1b,
             const float* __restrict__ Wfc,  const float* __restrict__ bfc,
             const float* __restrict__ bn2g, const float* __restrict__ bn2b,
             const float* __restrict__ Wcls, const float* __restrict__ bcls,
             float* __restrict__ out) {
    __shared__ float sA[128 * 65];
    __shared__ float red[256], red2[256];
    __shared__ float s_s[64], s_t[64];
    int tid = threadIdx.x;
    int c = tid & 63, rr = tid >> 6;

    for (int i = tid; i < 128 * 64; i += 256)
        sA[(i >> 6) * 65 + (i & 63)] = g_hg[i];
    __syncthreads();

    float s = 0.f, q = 0.f;
    for (int r = rr; r < 128; r += 4) {
        float v = sA[r * 65 + c];
        s += v; q += v * v;
    }
    red[tid] = s; red2[tid] = q;
    __syncthreads();
    if (tid < 64) {
        float S = red [tid] + red [tid + 64] + red [tid + 128] + red [tid + 192];
        float Q = red2[tid] + red2[tid + 64] + red2[tid + 128] + red2[tid + 192];
        float mu = S * (1.f / 128.f);
        float var = fmaxf(Q * (1.f / 128.f) - mu * mu, 0.f);
        float inv = rsqrtf(var + EPSBN);
        float sc = inv * bn1g[tid];
        s_s[tid] = sc;
        s_t[tid] = bn1b[tid] - mu * sc;
    }
    __syncthreads();
    for (int r = rr; r < 128; r += 4)
        sA[r * 65 + c] = sA[r * 65 + c] * s_s[c] + s_t[c];
    __syncthreads();

    float wreg[64];
    #pragma unroll
    for (int k = 0; k < 64; k++) wreg[k] = Wfc[k * 64 + c];
    float acc[32];
    for (int ri = 0; ri < 32; ri++) {
        int r = rr + ri * 4;
        float a = bfc[c];
        #pragma unroll
        for (int k = 0; k < 64; k++) a = fmaf(sA[r * 65 + k], wreg[k], a);
        acc[ri] = fmaxf(a, 0.f);
    }
    __syncthreads();
    for (int ri = 0; ri < 32; ri++) sA[(rr + ri * 4) * 65 + c] = acc[ri];
    __syncthreads();

    s = 0.f; q = 0.f;
    for (int r = rr; r < 128; r += 4) {
        float v = sA[r * 65 + c];
        s += v; q += v * v;
    }
    red[tid] = s; red2[tid] = q;
    __syncthreads();
    if (tid < 64) {
        float S = red [tid] + red [tid + 64] + red [tid + 128] + red [tid + 192];
        float Q = red2[tid] + red2[tid + 64] + red2[tid + 128] + red2[tid + 192];
        float mu = S * (1.f / 128.f);
        float var = fmaxf(Q * (1.f / 128.f) - mu * mu, 0.f);
        float inv = rsqrtf(var + EPSBN);
        float sc = inv * bn2g[tid];
        s_s[tid] = sc;
        s_t[tid] = bn2b[tid] - mu * sc;
    }
    __syncthreads();

    if (tid < 128) {
        int r = tid;
        float logits[10];
        #pragma unroll
        for (int j = 0; j < 10; j++) logits[j] = bcls[j];
        for (int k = 0; k < 64; k++) {
            float v = sA[r * 65 + k] * s_s[k] + s_t[k];
            #pragma unroll
            for (int j = 0; j < 10; j++)
                logits[j] = fmaf(v, Wcls[k * 10 + j], logits[j]);
        }
        float m = logits[0];
        #pragma unroll
        for (int j = 1; j < 10; j++) m = fmaxf(m, logits[j]);
        float se = 0.f;
        #pragma unroll
        for (int j = 0; j < 10; j++) se += expf(logits[j] - m);
        float lse = logf(se) + m;
        #pragma unroll
        for (int j = 0; j < 10; j++) out[r * 10 + j] = logits[j] - lse;
    }
}

// ---------------- host launch ----------------
extern "C" void kernel_launch(void* const* d_in, const int* in_sizes, int n_in,
                              void* d_out, int out_size) {
    const float* x         = (const float*)d_in[0];
    const int*   ei        = (const int*)  d_in[1];
    const int*   batch     = (const int*)  d_in[2];
    const float* bn_feat_g = (const float*)d_in[3];
    const float* bn_feat_b = (const float*)d_in[4];
    const float* W_feat    = (const float*)d_in[5];
    const float* b_feat    = (const float*)d_in[6];
    const float* conv_bn_g = (const float*)d_in[7];
    const float* conv_bn_b = (const float*)d_in[8];
    const float* conv_W    = (const float*)d_in[9];
    const float* conv_b    = (const float*)d_in[10];
    const float* bn_fc_g   = (const float*)d_in[11];
    const float* bn_fc_b   = (const float*)d_in[12];
    const float* W_fc      = (const float*)d_in[13];
    const float* b_fc      = (const float*)d_in[14];
    const float* bn_hid_g  = (const float*)d_in[15];
    const float* bn_hid_b  = (const float*)d_in[16];
    const float* W_cls     = (const float*)d_in[17];
    const float* b_cls     = (const float*)d_in[18];
    float* out = (float*)d_out;

    void *pb0, *pb1, *pWp_v, *pbias_v;
    cudaGetSymbolAddress(&pb0,    g_h);
    cudaGetSymbolAddress(&pb1,    g_hw);
    cudaGetSymbolAddress(&pWp_v,  g_Wp);
    cudaGetSymbolAddress(&pbias_v, g_bias);
    float* buf[2] = {(float*)pb0, (float*)pb1};
    float* pWp   = (float*)pWp_v;
    float* pbias = (float*)pbias_v;

    const int* src = ei;
    const int* dst = ei + EE;

    const int nbScan = (NN + 1023) / 1024;
    const int nbNode = (NN + 255) / 256;
    const int nbEdge = (EE + 255) / 256;
    const int nbStat = (NN + 511) / 512;
    const int nbGemm = (NN + 127) / 128;
    const int nbPool = (((NN + 15) / 16) * 32 + 255) / 256;

    // ---- CSR build ----
    k_zero_deg<<<nbNode, 256>>>();
    k_hist<<<nbEdge, 256>>>(src, dst);
    k_dis<<<nbNode, 256>>>();
    k_scan1<<<nbScan, 1024>>>();
    k_scan2<<<1, 1>>>(nbScan);
    k_scan3<<<nbScan, 1024>>>();
    k_fill<<<nbEdge, 256>>>(src, dst);

    // ---- feat layer: h = relu(BN(x) @ W_feat + b_feat), stats fused ----
    k_colstats<<<nbStat, 256>>>(x, NN);
    k_fold_feat<<<1, 64>>>(bn_feat_g, bn_feat_b, W_feat, b_feat);
    k_fused<<<nbGemm, 256>>>(x, pWp, pbias, buf[0], 1, 0);

    // ---- conv layers: fused agg+GEMM, double-buffered ----
    for (int l = 0; l < LL; l++) {
        k_scale<<<1, 64>>>(conv_bn_g + l * HH, conv_bn_b + l * HH);
        k_fused<<<nbGemm, 256>>>(buf[l & 1], conv_W + l * HH * HH,
                                 conv_b + l * HH, buf[(l + 1) & 1],
                                 (l < LL - 1) ? 1 : 0, 1);
    }

    // ---- pool + head ----
    k_zerohg<<<32, 256>>>();
    k_pool<<<nbPool, 256>>>(batch, buf[LL & 1]);
    k_final<<<1, 256>>>(bn_fc_g, bn_fc_b, W_fc, b_fc,
                        bn_hid_g, bn_hid_b, W_cls, b_cls, out);
}

// round 4
// speedup vs baseline: 1.2813x; 1.2019x over previous
#include <cuda_runtime.h>
#include <math.h>

#define NN 100000
#define EE 1200000
#define CC 64
#define HH 64
#define OUTC 10
#define GG 128
#define LL 3
#define EPSBN 1e-5f

// ---------------- scratch (device globals) ----------------
__device__ float g_h [NN * HH];    // node features h
__device__ float g_aw[NN * HH];    // aggregated+BN'd features (GEMM input)
__device__ int   g_outdeg[NN];
__device__ int   g_indeg [NN];
__device__ int   g_rowptr[NN + 1];
__device__ int   g_cur   [NN];
__device__ int   g_col   [EE];
__device__ float g_dis   [NN];
__device__ int   g_bsum  [128];
__device__ int   g_boff  [128];
__device__ float g_stat_s[4 * 64]; // per-layer column-sum slots
__device__ float g_stat_q[4 * 64]; // per-layer column-sumsq slots
__device__ float g_hg    [GG * HH];

// ---------------- setup: degrees, stats zero, CSR ----------------
__global__ void k_zero_deg() {
    int i = blockIdx.x * blockDim.x + threadIdx.x;
    if (i < NN) { g_outdeg[i] = 0; g_indeg[i] = 0; }
    if (i < 256) { g_stat_s[i] = 0.f; g_stat_q[i] = 0.f; }
    if (i < GG * HH) g_hg[i] = 0.f;
}

__global__ void k_hist(const int* __restrict__ src, const int* __restrict__ dst) {
    int e = blockIdx.x * blockDim.x + threadIdx.x;
    if (e < EE) {
        atomicAdd(&g_indeg[dst[e]], 1);
        atomicAdd(&g_outdeg[src[e]], 1);
    }
}

__global__ void k_scan1() {
    __shared__ int sb[1024];
    int t = threadIdx.x;
    int i = blockIdx.x * 1024 + t;
    int v = (i < NN) ? g_indeg[i] : 0;
    sb[t] = v;
    __syncthreads();
    for (int off = 1; off < 1024; off <<= 1) {
        int x = (t >= off) ? sb[t - off] : 0;
        __syncthreads();
        sb[t] += x;
        __syncthreads();
    }
    if (i < NN) g_rowptr[i] = sb[t] - v;
    if (t == 1023) g_bsum[blockIdx.x] = sb[1023];
}

__global__ void k_scan2(int nb) {
    int run = 0;
    for (int b = 0; b < nb; b++) { g_boff[b] = run; run += g_bsum[b]; }
    g_rowptr[NN] = run;
}

__global__ void k_scan3() {
    int i = blockIdx.x * 1024 + threadIdx.x;
    if (i < NN) {
        int v = g_rowptr[i] + g_boff[blockIdx.x];
        g_rowptr[i] = v;
        g_cur[i] = v;
        g_dis[i] = rsqrtf((float)g_outdeg[i] + 1.0f);
    }
}

__global__ void k_fill(const int* __restrict__ src, const int* __restrict__ dst) {
    int e = blockIdx.x * blockDim.x + threadIdx.x;
    if (e < EE) {
        int d = dst[e];
        int p = atomicAdd(&g_cur[d], 1);
        g_col[p] = src[e];
    }
}

// ---------------- column stats for x (slot 0) ----------------
__global__ void k_colstats(const float* __restrict__ A) {
    __shared__ float rs[256], rq[256];
    int c  = threadIdx.x & 63;
    int rr = threadIdx.x >> 6;
    int rbeg = blockIdx.x * 512;
    int rend = rbeg + 512; if (rend > NN) rend = NN;
    float s = 0.f, q = 0.f;
    for (int r = rbeg + rr; r < rend; r += 4) {
        float v = A[(size_t)r * 64 + c];
        s += v; q += v * v;
    }
    rs[threadIdx.x] = s; rq[threadIdx.x] = q;
    __syncthreads();
    if (threadIdx.x < 64) {
        float S = rs[threadIdx.x] + rs[threadIdx.x + 64] + rs[threadIdx.x + 128] + rs[threadIdx.x + 192];
        float Q = rq[threadIdx.x] + rq[threadIdx.x + 64] + rq[threadIdx.x + 128] + rq[threadIdx.x + 192];
        atomicAdd(&g_stat_s[threadIdx.x], S);
        atomicAdd(&g_stat_q[threadIdx.x], Q);
    }
}

// ---------------- GEMM: out = relu(A' @ W + bias); A' optionally BN-affine of A ----------------
// foldSlot >= 0: apply per-input-column affine (from stat slot + gam/bet) while staging sA
// statSlot >= 0: accumulate output column stats into that slot
__global__ __launch_bounds__(256)
void k_gemm(const float* __restrict__ A, const float* __restrict__ W,
            const float* __restrict__ bias, float* __restrict__ out,
            int statSlot, int foldSlot,
            const float* __restrict__ gam, const float* __restrict__ bet) {
    __shared__ float sA[64 * 128];   // k-major (transposed) A-tile
    __shared__ float sW[64 * 64];
    __shared__ float s_s[64], s_t[64];
    int tid = threadIdx.x;
    int rowBase = blockIdx.x * 128;

    if (foldSlot >= 0) {
        if (tid < 64) {
            float invn = 1.0f / (float)NN;
            float mu  = g_stat_s[foldSlot * 64 + tid] * invn;
            float var = fmaxf(g_stat_q[foldSlot * 64 + tid] * invn - mu * mu, 0.f);
            float sc = rsqrtf(var + EPSBN) * gam[tid];
            s_s[tid] = sc;
            s_t[tid] = bet[tid] - mu * sc;
        }
        __syncthreads();
    }

    for (int i = tid * 4; i < 4096; i += 1024)
        *(float4*)(sW + i) = *(const float4*)(W + i);

    int lane = tid & 31, wid = tid >> 5;
    int k0 = wid * 8;
    float fs[8], ft[8];
    #pragma unroll
    for (int j = 0; j < 8; j++) {
        fs[j] = (foldSlot >= 0) ? s_s[k0 + j] : 1.f;
        ft[j] = (foldSlot >= 0) ? s_t[k0 + j] : 0.f;
    }
    #pragma unroll
    for (int rp = 0; rp < 4; rp++) {
        int r = rp * 32 + lane;
        int grow = rowBase + r;
        float4 v0 = make_float4(0.f, 0.f, 0.f, 0.f), v1 = v0;
        if (grow < NN) {
            const float4* p = (const float4*)(A + (size_t)grow * 64 + k0);
            v0 = p[0]; v1 = p[1];
        }
        sA[(k0 + 0) * 128 + r] = v0.x * fs[0] + ft[0];
        sA[(k0 + 1) * 128 + r] = v0.y * fs[1] + ft[1];
        sA[(k0 + 2) * 128 + r] = v0.z * fs[2] + ft[2];
        sA[(k0 + 3) * 128 + r] = v0.w * fs[3] + ft[3];
        sA[(k0 + 4) * 128 + r] = v1.x * fs[4] + ft[4];
        sA[(k0 + 5) * 128 + r] = v1.y * fs[5] + ft[5];
        sA[(k0 + 6) * 128 + r] = v1.z * fs[6] + ft[6];
        sA[(k0 + 7) * 128 + r] = v1.w * fs[7] + ft[7];
    }
    __syncthreads();

    int cx = (tid & 15) * 4;   // 4 output cols
    int ry = (tid >> 4) * 8;   // 8 output rows
    float acc[8][4];
    #pragma unroll
    for (int i = 0; i < 8; i++)
        #pragma unroll
        for (int j = 0; j < 4; j++) acc[i][j] = 0.f;

    #pragma unroll
    for (int k = 0; k < 64; k++) {
        float4 w  = *(const float4*)(sW + k * 64 + cx);
        float4 a0 = *(const float4*)(sA + k * 128 + ry);
        float4 a1 = *(const float4*)(sA + k * 128 + ry + 4);
        float a[8] = {a0.x, a0.y, a0.z, a0.w, a1.x, a1.y, a1.z, a1.w};
        #pragma unroll
        for (int i = 0; i < 8; i++) {
            acc[i][0] = fmaf(a[i], w.x, acc[i][0]);
            acc[i][1] = fmaf(a[i], w.y, acc[i][1]);
            acc[i][2] = fmaf(a[i], w.z, acc[i][2]);
            acc[i][3] = fmaf(a[i], w.w, acc[i][3]);
        }
    }

    float b0 = bias[cx], b1 = bias[cx + 1], b2 = bias[cx + 2], b3 = bias[cx + 3];
    float cs[4] = {0.f, 0.f, 0.f, 0.f}, cq[4] = {0.f, 0.f, 0.f, 0.f};
    #pragma unroll
    for (int i = 0; i < 8; i++) {
        int grow = rowBase + ry + i;
        if (grow < NN) {
            float4 o;
            o.x = fmaxf(acc[i][0] + b0, 0.f);
            o.y = fmaxf(acc[i][1] + b1, 0.f);
            o.z = fmaxf(acc[i][2] + b2, 0.f);
            o.w = fmaxf(acc[i][3] + b3, 0.f);
            *(float4*)(out + (size_t)grow * 64 + cx) = o;
            cs[0] += o.x; cq[0] += o.x * o.x;
            cs[1] += o.y; cq[1] += o.y * o.y;
            cs[2] += o.z; cq[2] += o.z * o.z;
            cs[3] += o.w; cq[3] += o.w * o.w;
        }
    }

    if (statSlot >= 0) {
        __syncthreads();              // sA dead; reuse as scratch
        float* sredS = sA;
        float* sredQ = sA + 512;
        #pragma unroll
        for (int j = 0; j < 4; j++) {
            cs[j] += __shfl_xor_sync(0xFFFFFFFFu, cs[j], 16);
            cq[j] += __shfl_xor_sync(0xFFFFFFFFu, cq[j], 16);
        }
        if (lane < 16) {
            #pragma unroll
            for (int j = 0; j < 4; j++) {
                sredS[wid * 64 + cx + j] = cs[j];
                sredQ[wid * 64 + cx + j] = cq[j];
            }
        }
        __syncthreads();
        if (tid < 64) {
            float S = 0.f, Q = 0.f;
            #pragma unroll
            for (int w = 0; w < 8; w++) { S += sredS[w * 64 + tid]; Q += sredQ[w * 64 + tid]; }
            atomicAdd(&g_stat_s[statSlot * 64 + tid], S);
            atomicAdd(&g_stat_q[statSlot * 64 + tid], Q);
        }
    }
}

// ---------------- aggregation (warp per node): Aout = sc∘(Σ w·h[src] + di²·h[i]) + ws·sh ----------------
__global__ __launch_bounds__(256)
void k_agg(const float* __restrict__ Ain, float* __restrict__ Aout,
           int slot, const float* __restrict__ gam, const float* __restrict__ bet) {
    __shared__ float s_sc[64], s_sh[64];
    if (threadIdx.x < 64) {
        float invn = 1.0f / (float)NN;
        float mu  = g_stat_s[slot * 64 + threadIdx.x] * invn;
        float var = fmaxf(g_stat_q[slot * 64 + threadIdx.x] * invn - mu * mu, 0.f);
        float sc = rsqrtf(var + EPSBN) * gam[threadIdx.x];
        s_sc[threadIdx.x] = sc;
        s_sh[threadIdx.x] = bet[threadIdx.x] - mu * sc;
    }
    __syncthreads();

    int gtid = blockIdx.x * 256 + threadIdx.x;
    int i = gtid >> 5;
    int lane = gtid & 31;
    if (i >= NN) return;
    int c0 = lane * 2;
    float di = g_dis[i];
    int e = g_rowptr[i], end = g_rowptr[i + 1];
    float a0 = 0.f, a1 = 0.f, ws = 0.f;

    for (; e + 4 <= end; e += 4) {
        int s0 = g_col[e], s1 = g_col[e + 1], s2 = g_col[e + 2], s3 = g_col[e + 3];
        float w0 = g_dis[s0], w1 = g_dis[s1], w2 = g_dis[s2], w3 = g_dis[s3];
        float2 v0 = *(const float2*)&Ain[(size_t)s0 * 64 + c0];
        float2 v1 = *(const float2*)&Ain[(size_t)s1 * 64 + c0];
        float2 v2 = *(const float2*)&Ain[(size_t)s2 * 64 + c0];
        float2 v3 = *(const float2*)&Ain[(size_t)s3 * 64 + c0];
        w0 *= di; w1 *= di; w2 *= di; w3 *= di;
        a0 = fmaf(w0, v0.x, a0); a1 = fmaf(w0, v0.y, a1);
        a0 = fmaf(w1, v1.x, a0); a1 = fmaf(w1, v1.y, a1);
        a0 = fmaf(w2, v2.x, a0); a1 = fmaf(w2, v2.y, a1);
        a0 = fmaf(w3, v3.x, a0); a1 = fmaf(w3, v3.y, a1);
        ws += w0 + w1 + w2 + w3;
    }
    for (; e < end; e++) {
        int s = g_col[e];
        float w = di * g_dis[s];
        float2 v = *(const float2*)&Ain[(size_t)s * 64 + c0];
        a0 = fmaf(w, v.x, a0);
        a1 = fmaf(w, v.y, a1);
        ws += w;
    }
    {   // self loop
        float w = di * di;
        float2 v = *(const float2*)&Ain[(size_t)i * 64 + c0];
        a0 = fmaf(w, v.x, a0);
        a1 = fmaf(w, v.y, a1);
        ws += w;
    }
    float o0 = s_sc[c0]     * a0 + ws * s_sh[c0];
    float o1 = s_sc[c0 + 1] * a1 + ws * s_sh[c0 + 1];
    *(float2*)&Aout[(size_t)i * 64 + c0] = make_float2(o0, o1);
}

// ---------------- pooling ----------------
__global__ void k_pool(const int* __restrict__ batch, const float* __restrict__ hin) {
    int gtid = blockIdx.x * 256 + threadIdx.x;
    int warp = gtid >> 5;
    int lane = gtid & 31;
    int n0 = warp * 16;
    if (n0 >= NN) return;
    int nend = n0 + 16; if (nend > NN) nend = NN;
    int c0 = lane * 2;
    float a0 = 0.f, a1 = 0.f;
    int curg = batch[n0];
    for (int nd = n0; nd < nend; nd++) {
        int g = batch[nd];
        if (g != curg) {
            atomicAdd(&g_hg[curg * 64 + c0],     a0);
            atomicAdd(&g_hg[curg * 64 + c0 + 1], a1);
            a0 = 0.f; a1 = 0.f; curg = g;
        }
        float2 v = *(const float2*)&hin[(size_t)nd * 64 + c0];
        a0 += v.x; a1 += v.y;
    }
    atomicAdd(&g_hg[curg * 64 + c0],     a0);
    atomicAdd(&g_hg[curg * 64 + c0 + 1], a1);
}

// ---------------- final head ----------------
__global__ __launch_bounds__(256, 1)
void k_final(const float* __restrict__ bn1g, const float* __restrict__ bn1b,
             const float* __restrict__ Wfc,  const float* __restrict__ bfc,
             const float* __restrict__ bn2g, const float* __restrict__ bn2b,
             const float* __restrict__ Wcls, const float* __restrict__ bcls,
             float* __restrict__ out) {
    __shared__ float sA[128 * 65];
    __shared__ float red[256], red2[256];
    __shared__ float s_s[64], s_t[64];
    int tid = threadIdx.x;
    int c = tid & 63, rr = tid >> 6;

    for (int i = tid; i < 128 * 64; i += 256)
        sA[(i >> 6) * 65 + (i & 63)] = g_hg[i];
    __syncthreads();

    float s = 0.f, q = 0.f;
    for (int r = rr; r < 128; r += 4) {
        float v = sA[r * 65 + c];
        s += v; q += v * v;
    }
    red[tid] = s; red2[tid] = q;
    __syncthreads();
    if (tid < 64) {
        float S = red [tid] + red [tid + 64] + red [tid + 128] + red [tid + 192];
        float Q = red2[tid] + red2[tid + 64] + red2[tid + 128] + red2[tid + 192];
        float mu = S * (1.f / 128.f);
        float var = fmaxf(Q * (1.f / 128.f) - mu * mu, 0.f);
        float inv = rsqrtf(var + EPSBN);
        float sc = inv * bn1g[tid];
        s_s[tid] = sc;
        s_t[tid] = bn1b[tid] - mu * sc;
    }
    __syncthreads();
    for (int r = rr; r < 128; r += 4)
        sA[r * 65 + c] = sA[r * 65 + c] * s_s[c] + s_t[c];
    __syncthreads();

    float wreg[64];
    #pragma unroll
    for (int k = 0; k < 64; k++) wreg[k] = Wfc[k * 64 + c];
    float acc[32];
    for (int ri = 0; ri < 32; ri++) {
        int r = rr + ri * 4;
        float a = bfc[c];
        #pragma unroll
        for (int k = 0; k < 64; k++) a = fmaf(sA[r * 65 + k], wreg[k], a);
        acc[ri] = fmaxf(a, 0.f);
    }
    __syncthreads();
    for (int ri = 0; ri < 32; ri++) sA[(rr + ri * 4) * 65 + c] = acc[ri];
    __syncthreads();

    s = 0.f; q = 0.f;
    for (int r = rr; r < 128; r += 4) {
        float v = sA[r * 65 + c];
        s += v; q += v * v;
    }
    red[tid] = s; red2[tid] = q;
    __syncthreads();
    if (tid < 64) {
        float S = red [tid] + red [tid + 64] + red [tid + 128] + red [tid + 192];
        float Q = red2[tid] + red2[tid + 64] + red2[tid + 128] + red2[tid + 192];
        float mu = S * (1.f / 128.f);
        float var = fmaxf(Q * (1.f / 128.f) - mu * mu, 0.f);
        float inv = rsqrtf(var + EPSBN);
        float sc = inv * bn2g[tid];
        s_s[tid] = sc;
        s_t[tid] = bn2b[tid] - mu * sc;
    }
    __syncthreads();

    if (tid < 128) {
        int r = tid;
        float logits[10];
        #pragma unroll
        for (int j = 0; j < 10; j++) logits[j] = bcls[j];
        for (int k = 0; k < 64; k++) {
            float v = sA[r * 65 + k] * s_s[k] + s_t[k];
            #pragma unroll
            for (int j = 0; j < 10; j++)
                logits[j] = fmaf(v, Wcls[k * 10 + j], logits[j]);
        }
        float m = logits[0];
        #pragma unroll
        for (int j = 1; j < 10; j++) m = fmaxf(m, logits[j]);
        float se = 0.f;
        #pragma unroll
        for (int j = 0; j < 10; j++) se += expf(logits[j] - m);
        float lse = logf(se) + m;
        #pragma unroll
        for (int j = 0; j < 10; j++) out[r * 10 + j] = logits[j] - lse;
    }
}

// ---------------- host launch ----------------
extern "C" void kernel_launch(void* const* d_in, const int* in_sizes, int n_in,
                              void* d_out, int out_size) {
    const float* x         = (const float*)d_in[0];
    const int*   ei        = (const int*)  d_in[1];
    const int*   batch     = (const int*)  d_in[2];
    const float* bn_feat_g = (const float*)d_in[3];
    const float* bn_feat_b = (const float*)d_in[4];
    const float* W_feat    = (const float*)d_in[5];
    const float* b_feat    = (const float*)d_in[6];
    const float* conv_bn_g = (const float*)d_in[7];
    const float* conv_bn_b = (const float*)d_in[8];
    const float* conv_W    = (const float*)d_in[9];
    const float* conv_b    = (const float*)d_in[10];
    const float* bn_fc_g   = (const float*)d_in[11];
    const float* bn_fc_b   = (const float*)d_in[12];
    const float* W_fc      = (const float*)d_in[13];
    const float* b_fc      = (const float*)d_in[14];
    const float* bn_hid_g  = (const float*)d_in[15];
    const float* bn_hid_b  = (const float*)d_in[16];
    const float* W_cls     = (const float*)d_in[17];
    const float* b_cls     = (const float*)d_in[18];
    float* out = (float*)d_out;

    void *ph_v, *paw_v;
    cudaGetSymbolAddress(&ph_v,  g_h);
    cudaGetSymbolAddress(&paw_v, g_aw);
    float* ph  = (float*)ph_v;
    float* paw = (float*)paw_v;

    const int* src = ei;
    const int* dst = ei + EE;

    const int nbScan = (NN + 1023) / 1024;
    const int nbNode = (NN + 255) / 256;
    const int nbEdge = (EE + 255) / 256;
    const int nbStat = (NN + 511) / 512;
    const int nbGemm = (NN + 127) / 128;
    const int nbAgg  = (NN * 32 + 255) / 256;
    const int nbPool = (((NN + 15) / 16) * 32 + 255) / 256;

    // ---- CSR build ----
    k_zero_deg<<<nbNode, 256>>>();
    k_hist<<<nbEdge, 256>>>(src, dst);
    k_scan1<<<nbScan, 1024>>>();
    k_scan2<<<1, 1>>>(nbScan);
    k_scan3<<<nbScan, 1024>>>();
    k_fill<<<nbEdge, 256>>>(src, dst);

    // ---- feat layer: h = relu(BN(x) @ W_feat + b_feat); x stats slot0, h stats slot1 ----
    k_colstats<<<nbStat, 256>>>(x);
    k_gemm<<<nbGemm, 256>>>(x, W_feat, b_feat, ph, 1, 0, bn_feat_g, bn_feat_b);

    // ---- conv layers: agg (BN from slot l+1) -> GEMM (stats into slot l+2) ----
    for (int l = 0; l < LL; l++) {
        k_agg<<<nbAgg, 256>>>(ph, paw, l + 1, conv_bn_g + l * HH, conv_bn_b + l * HH);
        k_gemm<<<nbGemm, 256>>>(paw, conv_W + l * HH * HH, conv_b + l * HH, ph,
                                (l < LL - 1) ? (l + 2) : -1, -1,
                                (const float*)0, (const float*)0);
    }

    // ---- pool + head ----
    k_pool<<<nbPool, 256>>>(batch, ph);
    k_final<<<1, 256>>>(bn_fc_g, bn_fc_b, W_fc, b_fc,
                        bn_hid_g, bn_hid_b, W_cls, b_cls, out);
}